// round 14
// baseline (speedup 1.0000x reference)
#include <cuda_runtime.h>
#include <cuda_bf16.h>
#include <cstdint>

// ---------------------------------------------------------------------------
// EGNN layer, fused, f32x2 (FFMA2) GEMV path + algebraic layer-1 hoisting.
//   Layer 1 of the edge MLP is linear in the gathered features:
//     e_in @ W_e1 = x[dst]@W1a + x[src]@W1b + r2*w_r2 + ea*w_ea
//   so P = x@W1a and Q = x@W1b are precomputed per NODE (pre_kernel), and the
//   per-EDGE layer 1 is just silu(P[dst]+Q[src]+r2*w_r2+ea*w_ea+b1).
//   edge_kernel runs the 128-deep layer-2 GEMV + epilogue, 16 edges/warp so
//   each 64KB sweep of W2 through the SMEM crossbar is amortized over 16
//   edges (weight crossbar tax halved vs ED=8).
// Weights stored k-pair interleaved with a 16B XOR swizzle -> conflict-free
// warp-wide LDS.128; accumulation is k-pairwise in f32x2 lanes.
// ---------------------------------------------------------------------------

#define NMAX 50048

#define NW_P 8
#define TPB_P (NW_P * 32)   // 256
#define ND_P 8              // nodes per warp (pre)

#define NW_E 8
#define TPB_E (NW_E * 32)   // 256
#define ED 16               // edges per warp

#define NW_N 8
#define TPB_N (NW_N * 32)   // 256
#define ND 8                // nodes per warp

__device__ __align__(16) float g_msum[(size_t)NMAX * 128];
__device__ __align__(16) float g_coord[(size_t)NMAX * 3];
__device__ __align__(16) float g_deg[NMAX];
__device__ __align__(16) float g_P[(size_t)NMAX * 128];
__device__ __align__(16) float g_Q[(size_t)NMAX * 128];
__device__ int g_or;        // 0 => indices are int64, nonzero => int32

__device__ __forceinline__ float silu_f(float v) {
    return __fdividef(v, 1.0f + __expf(-v));
}

__device__ __forceinline__ void red_add_v4(float* addr, float4 v) {
    asm volatile("red.global.add.v4.f32 [%0], {%1,%2,%3,%4};"
                 :: "l"(addr), "f"(v.x), "f"(v.y), "f"(v.z), "f"(v.w)
                 : "memory");
}

__device__ __forceinline__ void fma2(unsigned long long& a,
                                     unsigned long long v,
                                     unsigned long long w) {
    asm("fma.rn.f32x2 %0, %1, %2, %0;" : "+l"(a) : "l"(v), "l"(w));
}
__device__ __forceinline__ float lohi_sum(unsigned long long a) {
    float lo, hi;
    asm("mov.b64 {%0,%1}, %2;" : "=f"(lo), "=f"(hi) : "l"(a));
    return lo + hi;
}

// Swizzled index for k-pair interleaved weight storage (see round 11/12).
// acc[g][i] ends up holding output j = lane*4 + i.
__device__ __forceinline__ int wswz(int k, int j) {
    int k2 = k >> 1, p = k & 1;
    int col = j * 2 + p;             // 0..255
    int L = col >> 3;                // owning lane
    int o = col & 7;
    int c = o >> 2;                  // chunk 0/1
    int pos = o & 3;
    return k2 * 256 + (L * 2 + (c ^ ((L >> 2) & 1))) * 4 + pos;
}

// One k4 step (2 k-pairs = 4 k values) of the packed GEMV for NA accumulators.
template<int NA>
__device__ __forceinline__ void gemv_step(const float* __restrict__ wrow,
                                          int s4,
                                          const float* __restrict__ act,
                                          int actStride, int kofs,
                                          unsigned long long (*acc)[4]) {
    ulonglong2 a0 = *(const ulonglong2*)(wrow + s4);
    ulonglong2 c0 = *(const ulonglong2*)(wrow + 4 - s4);
    ulonglong2 a1 = *(const ulonglong2*)(wrow + 256 + s4);
    ulonglong2 c1 = *(const ulonglong2*)(wrow + 256 + 4 - s4);
    #pragma unroll
    for (int g = 0; g < NA; g++) {
        ulonglong2 v = *(const ulonglong2*)(act + g * actStride + kofs);
        fma2(acc[g][0], v.x, a0.x); fma2(acc[g][1], v.x, a0.y);
        fma2(acc[g][2], v.x, c0.x); fma2(acc[g][3], v.x, c0.y);
        fma2(acc[g][0], v.y, a1.x); fma2(acc[g][1], v.y, a1.y);
        fma2(acc[g][2], v.y, c1.x); fma2(acc[g][3], v.y, c1.y);
    }
}

// ------------------------------- zero ---------------------------------------
__global__ void zero_kernel(int n) {
    int i = blockIdx.x * blockDim.x + threadIdx.x;
    int stride = gridDim.x * blockDim.x;
    if (i == 0) g_or = 0;
    int total = n * 128;
    for (int j = i; j < total; j += stride) g_msum[j] = 0.0f;
    for (int j = i; j < n * 3; j += stride) g_coord[j] = 0.0f;
    for (int j = i; j < n;     j += stride) g_deg[j]   = 0.0f;
}

// ------------------------------- detect --------------------------------------
__global__ void detect_kernel(const unsigned int* w, int E) {
    unsigned acc = 0;
    int lim = E < 8192 ? E : 8192;
    for (int i = blockIdx.x * blockDim.x + threadIdx.x; i < lim;
         i += gridDim.x * blockDim.x)
        acc |= w[2 * i + 1];
    if (acc) atomicOr(&g_or, 1);
}

// ------------------------------- pre ----------------------------------------
// P = x @ W1[0:128,:],  Q = x @ W1[128:256,:]   (no bias)
__global__ __launch_bounds__(TPB_P, 1)
void pre_kernel(const float* __restrict__ x, const float* __restrict__ We1,
                int N)
{
    extern __shared__ float sm[];
    float* sWa = sm;
    float* sWb = sWa + 64 * 256;
    float* sE  = sWb + 64 * 256;

    const int tid = threadIdx.x;
    for (int idx = tid; idx < 128 * 128; idx += TPB_P) {
        int k = idx >> 7, j = idx & 127;
        int d = wswz(k, j);
        sWa[d] = We1[idx];
        sWb[d] = We1[128 * 128 + idx];
    }
    __syncthreads();

    const int lane = tid & 31;
    const int w    = tid >> 5;
    float* eb = sE + w * (ND_P * 128);

    const int wofs = lane * 8;
    const int s4   = ((lane >> 2) & 1) * 4;

    const int bstride = gridDim.x * NW_P * ND_P;
    for (int b0 = (blockIdx.x * NW_P + w) * ND_P; b0 < N; b0 += bstride) {
        __syncwarp();
        #pragma unroll
        for (int g = 0; g < ND_P; g++) {
            int ng = b0 + g; if (ng >= N) ng = N - 1;
            *(float4*)(eb + g * 128 + lane * 4) =
                *(const float4*)(x + (size_t)ng * 128 + lane * 4);
        }
        __syncwarp();

        unsigned long long acc[ND_P][4];
        #pragma unroll
        for (int g = 0; g < ND_P; g++)
            acc[g][0] = acc[g][1] = acc[g][2] = acc[g][3] = 0ull;
        #pragma unroll 4
        for (int k4 = 0; k4 < 32; k4++)
            gemv_step<ND_P>(sWa + (k4 * 2) * 256 + wofs, s4, eb, 128, k4 * 4, acc);
        #pragma unroll
        for (int g = 0; g < ND_P; g++) {
            int ng = b0 + g;
            if (ng < N) {
                float4 o;
                o.x = lohi_sum(acc[g][0]); o.y = lohi_sum(acc[g][1]);
                o.z = lohi_sum(acc[g][2]); o.w = lohi_sum(acc[g][3]);
                *(float4*)(g_P + (size_t)ng * 128 + lane * 4) = o;
            }
            acc[g][0] = acc[g][1] = acc[g][2] = acc[g][3] = 0ull;
        }

        #pragma unroll 4
        for (int k4 = 0; k4 < 32; k4++)
            gemv_step<ND_P>(sWb + (k4 * 2) * 256 + wofs, s4, eb, 128, k4 * 4, acc);
        #pragma unroll
        for (int g = 0; g < ND_P; g++) {
            int ng = b0 + g;
            if (ng < N) {
                float4 o;
                o.x = lohi_sum(acc[g][0]); o.y = lohi_sum(acc[g][1]);
                o.z = lohi_sum(acc[g][2]); o.w = lohi_sum(acc[g][3]);
                *(float4*)(g_Q + (size_t)ng * 128 + lane * 4) = o;
            }
        }
    }
}

// ------------------------------- edge ---------------------------------------
// SMEM floats: sW2[64*256]=16384  sWc/sb2/sb1/swr/swe[640]
//              eb[NW_E*ED*128]=16384  -> 33,408 floats = 133,632 B
__global__ __launch_bounds__(TPB_E, 1)
void edge_kernel(const float* __restrict__ pos,
                 const int* __restrict__ ei32, const long long* __restrict__ ei64,
                 const float* __restrict__ eattr, const float* __restrict__ s,
                 const float* __restrict__ We1, const float* __restrict__ be1,
                 const float* __restrict__ We2, const float* __restrict__ be2,
                 const float* __restrict__ Wc,  const float* __restrict__ bc,
                 int E, int Nn)
{
    extern __shared__ float sm[];
    float* sW2 = sm;                  // 64 k2-rows x 256
    float* sWc = sW2 + 64 * 256;
    float* sb2 = sWc + 128;
    float* sb1 = sb2 + 128;
    float* swr = sb1 + 128;           // W1 row 256 (r2 weights)
    float* swe = swr + 128;           // W1 row 257 (edge_attr weights)
    float* sE  = swe + 128;

    const int tid = threadIdx.x;
    for (int idx = tid; idx < 128 * 128; idx += TPB_E) {
        int k = idx >> 7, j = idx & 127;
        sW2[wswz(k, j)] = We2[idx];
    }
    for (int i = tid; i < 128; i += TPB_E) {
        sWc[i] = Wc[i]; sb2[i] = be2[i]; sb1[i] = be1[i];
        swr[i] = We1[256 * 128 + i];
        swe[i] = We1[257 * 128 + i];
    }
    __syncthreads();

    const bool idx64 = (g_or == 0);
    const float bcv  = bc[0];
    const int lane   = tid & 31;
    const int w      = tid >> 5;
    float* eb = sE + w * (ED * 128);

    const int wofs = lane * 8;
    const int s4   = ((lane >> 2) & 1) * 4;
    const float4 sb2v = *(const float4*)(sb2 + lane * 4);
    const float4 sb1v = *(const float4*)(sb1 + lane * 4);
    const float4 wrv  = *(const float4*)(swr + lane * 4);
    const float4 wev  = *(const float4*)(swe + lane * 4);
    const float4 wcv  = *(const float4*)(sWc + lane * 4);

    const long long bstride = (long long)gridDim.x * NW_E * ED;
    for (long long b0 = ((long long)blockIdx.x * NW_E + w) * ED;
         b0 < E; b0 += bstride) {

        // ---- lane-distributed per-edge metadata (lane g owns edge b0+g) ----
        long long e = b0 + lane;
        bool have = (lane < ED) && (e < (long long)E);
        int ss = 0, dd = 0;
        if (have) {
            if (idx64) { ss = (int)ei64[e]; dd = (int)ei64[E + e]; }
            else       { ss = ei32[e];      dd = ei32[E + e]; }
            if ((unsigned)ss >= (unsigned)Nn || (unsigned)dd >= (unsigned)Nn) {
                have = false; ss = 0; dd = 0;
            }
        }
        float dx = 0.f, dy = 0.f, dz = 0.f, r2 = 0.f, ea = 0.f, sg = 0.f;
        if (lane < ED) {
            dx = pos[dd * 3 + 0] - pos[ss * 3 + 0];
            dy = pos[dd * 3 + 1] - pos[ss * 3 + 1];
            dz = pos[dd * 3 + 2] - pos[ss * 3 + 2];
            r2 = dx * dx + dy * dy + dz * dz;
            ea = have ? eattr[e] : 0.0f;
            sg = s[ss];
        }
        const int okflag = have ? 1 : 0;

        // ---- layer-1 via hoisting: h = silu(P[dst] + Q[src] + r2*wr + ea*we + b1)
        __syncwarp();
        #pragma unroll
        for (int g = 0; g < ED; g++) {
            int dg  = __shfl_sync(0xffffffffu, dd, g);
            int sgi = __shfl_sync(0xffffffffu, ss, g);
            float r2g = __shfl_sync(0xffffffffu, r2, g);
            float eag = __shfl_sync(0xffffffffu, ea, g);
            float4 pv = *(const float4*)(g_P + (size_t)dg  * 128 + lane * 4);
            float4 qv = *(const float4*)(g_Q + (size_t)sgi * 128 + lane * 4);
            float4 h;
            h.x = silu_f(fmaf(r2g, wrv.x, fmaf(eag, wev.x, pv.x + qv.x + sb1v.x)));
            h.y = silu_f(fmaf(r2g, wrv.y, fmaf(eag, wev.y, pv.y + qv.y + sb1v.y)));
            h.z = silu_f(fmaf(r2g, wrv.z, fmaf(eag, wev.z, pv.z + qv.z + sb1v.z)));
            h.w = silu_f(fmaf(r2g, wrv.w, fmaf(eag, wev.w, pv.w + qv.w + sb1v.w)));
            *(float4*)(eb + g * 128 + lane * 4) = h;
        }
        __syncwarp();

        // ---- layer 2: 128 -> 128, f32x2, 16 edges share each weight sweep ----
        unsigned long long acc[ED][4];
        #pragma unroll
        for (int g = 0; g < ED; g++)
            acc[g][0] = acc[g][1] = acc[g][2] = acc[g][3] = 0ull;
        #pragma unroll 2
        for (int k4 = 0; k4 < 32; k4++)
            gemv_step<ED>(sW2 + (k4 * 2) * 256 + wofs, s4, eb, 128, k4 * 4, acc);

        // ---- epilogue: SiLU, s-gate, gamma, scatter ----
        float psel = 0.0f;
        #pragma unroll
        for (int g = 0; g < ED; g++) {
            float sgg = __shfl_sync(0xffffffffu, sg, g);
            float4 mg;
            mg.x = silu_f(lohi_sum(acc[g][0]) + sb2v.x) * sgg;
            mg.y = silu_f(lohi_sum(acc[g][1]) + sb2v.y) * sgg;
            mg.z = silu_f(lohi_sum(acc[g][2]) + sb2v.z) * sgg;
            mg.w = silu_f(lohi_sum(acc[g][3]) + sb2v.w) * sgg;

            float p = mg.x * wcv.x + mg.y * wcv.y + mg.z * wcv.z + mg.w * wcv.w;
            #pragma unroll
            for (int o = 16; o; o >>= 1)
                p += __shfl_xor_sync(0xffffffffu, p, o);

            int okg = __shfl_sync(0xffffffffu, okflag, g);
            int dg  = __shfl_sync(0xffffffffu, dd, g);
            if (okg) red_add_v4(g_msum + (size_t)dg * 128 + lane * 4, mg);
            if (lane == g) psel = p;
        }
        if (lane < ED && have) {
            const float gam = psel + bcv;
            atomicAdd(g_coord + dd * 3 + 0, gam * dx);
            atomicAdd(g_coord + dd * 3 + 1, gam * dy);
            atomicAdd(g_coord + dd * 3 + 2, gam * dz);
            atomicAdd(g_deg + dd, 1.0f);
        }
    }
}

// ------------------------------- node ---------------------------------------
// SMEM floats: sWn1[128*256]=32768  sWn2[64*256]=16384  biases 256
//              sE[NW_N*ND*128]=8192  -> 57600 floats = 230,400 B
__global__ __launch_bounds__(TPB_N, 1)
void node_kernel(const float* __restrict__ x, const float* __restrict__ pos,
                 const float* __restrict__ Wn1, const float* __restrict__ bn1,
                 const float* __restrict__ Wn2, const float* __restrict__ bn2,
                 float* __restrict__ xout, float* __restrict__ posout,
                 int N)
{
    extern __shared__ float sm[];
    float* sW1 = sm;                  // 128 k2-rows x 256
    float* sW2 = sW1 + 128 * 256;     // 64 k2-rows x 256
    float* sb1 = sW2 + 64 * 256;
    float* sb2 = sb1 + 128;
    float* sE  = sb2 + 128;

    const int tid = threadIdx.x;
    for (int idx = tid; idx < 256 * 128; idx += TPB_N) {
        int k = idx >> 7, j = idx & 127;
        sW1[wswz(k, j)] = Wn1[idx];
    }
    for (int idx = tid; idx < 128 * 128; idx += TPB_N) {
        int k = idx >> 7, j = idx & 127;
        sW2[wswz(k, j)] = Wn2[idx];
    }
    for (int i = tid; i < 128; i += TPB_N) { sb1[i] = bn1[i]; sb2[i] = bn2[i]; }
    __syncthreads();

    const int lane = tid & 31;
    const int w    = tid >> 5;
    float* eb = sE + w * (ND * 128);

    const int wofs = lane * 8;
    const int s4   = ((lane >> 2) & 1) * 4;
    const float4 sb1v = *(const float4*)(sb1 + lane * 4);
    const float4 sb2v = *(const float4*)(sb2 + lane * 4);

    const int bstride = gridDim.x * NW_N * ND;
    for (int b0 = (blockIdx.x * NW_N + w) * ND; b0 < N; b0 += bstride) {

        int nm = b0 + lane;
        float inv = 1.0f;
        if (lane < ND && nm < N) inv = 1.0f / fmaxf(g_deg[nm], 1.0f);

        unsigned long long acc[ND][4];
        #pragma unroll
        for (int g = 0; g < ND; g++)
            acc[g][0] = acc[g][1] = acc[g][2] = acc[g][3] = 0ull;

        // ---- layer 1 phase A: rows 0..127 with x ----
        __syncwarp();
        #pragma unroll
        for (int g = 0; g < ND; g++) {
            int ng = b0 + g; if (ng >= N) ng = N - 1;
            *(float4*)(eb + g * 128 + lane * 4) =
                *(const float4*)(x + (size_t)ng * 128 + lane * 4);
        }
        __syncwarp();
        #pragma unroll 4
        for (int k4 = 0; k4 < 32; k4++)
            gemv_step<ND>(sW1 + (k4 * 2) * 256 + wofs, s4, eb, 128, k4 * 4, acc);

        // ---- layer 1 phase B: rows 128..255 with m_sum/deg ----
        __syncwarp();
        #pragma unroll
        for (int g = 0; g < ND; g++) {
            int ng = b0 + g; if (ng >= N) ng = N - 1;
            float ig = __shfl_sync(0xffffffffu, inv, g);
            float4 ms = *(const float4*)(g_msum + (size_t)ng * 128 + lane * 4);
            ms.x *= ig; ms.y *= ig; ms.z *= ig; ms.w *= ig;
            *(float4*)(eb + g * 128 + lane * 4) = ms;
        }
        __syncwarp();
        #pragma unroll 4
        for (int k4 = 0; k4 < 32; k4++)
            gemv_step<ND>(sW1 + ((k4 + 32) * 2) * 256 + wofs, s4, eb, 128, k4 * 4, acc);

        // ---- SiLU, stage h, layer 2 ----
        __syncwarp();
        #pragma unroll
        for (int g = 0; g < ND; g++) {
            float4 h;
            h.x = silu_f(lohi_sum(acc[g][0]) + sb1v.x);
            h.y = silu_f(lohi_sum(acc[g][1]) + sb1v.y);
            h.z = silu_f(lohi_sum(acc[g][2]) + sb1v.z);
            h.w = silu_f(lohi_sum(acc[g][3]) + sb1v.w);
            *(float4*)(eb + g * 128 + lane * 4) = h;
            acc[g][0] = acc[g][1] = acc[g][2] = acc[g][3] = 0ull;
        }
        __syncwarp();

        #pragma unroll 4
        for (int k4 = 0; k4 < 32; k4++)
            gemv_step<ND>(sW2 + (k4 * 2) * 256 + wofs, s4, eb, 128, k4 * 4, acc);

        #pragma unroll
        for (int g = 0; g < ND; g++) {
            int ng = b0 + g;
            if (ng < N) {
                float4 o;
                o.x = lohi_sum(acc[g][0]) + sb2v.x;
                o.y = lohi_sum(acc[g][1]) + sb2v.y;
                o.z = lohi_sum(acc[g][2]) + sb2v.z;
                o.w = lohi_sum(acc[g][3]) + sb2v.w;
                *(float4*)(xout + (size_t)ng * 128 + lane * 4) = o;
                float ig = __shfl_sync(0xffffffffu, inv, g);
                if (lane < 3)
                    posout[ng * 3 + lane] =
                        pos[ng * 3 + lane] + g_coord[ng * 3 + lane] * ig;
            }
        }
    }
}

// ------------------------------- launch --------------------------------------
extern "C" void kernel_launch(void* const* d_in, const int* in_sizes, int n_in,
                              void* d_out, int out_size) {
    const float* x     = (const float*)d_in[0];
    const float* pos   = (const float*)d_in[1];
    const void*  ei    = d_in[2];
    const float* eattr = (const float*)d_in[3];
    const float* s     = (const float*)d_in[4];
    const float* We1   = (const float*)d_in[5];
    const float* be1   = (const float*)d_in[6];
    const float* We2   = (const float*)d_in[7];
    const float* be2   = (const float*)d_in[8];
    const float* Wn1   = (const float*)d_in[9];
    const float* bn1   = (const float*)d_in[10];
    const float* Wn2   = (const float*)d_in[11];
    const float* bn2   = (const float*)d_in[12];
    const float* Wc    = (const float*)d_in[13];
    const float* bc    = (const float*)d_in[14];

    const int N = in_sizes[0] / 128;
    const int E = in_sizes[2] / 2;

    float* xout   = (float*)d_out;
    float* posout = (float*)d_out + (size_t)N * 128;

    int dev = 0, nsm = 148;
    cudaGetDevice(&dev);
    cudaDeviceGetAttribute(&nsm, cudaDevAttrMultiProcessorCount, dev);

    const size_t smem_pre  = (size_t)(64 * 256 + 64 * 256 +
                                      NW_P * ND_P * 128) * sizeof(float);  // 163,840
    const size_t smem_edge = (size_t)(64 * 256 + 5 * 128 +
                                      NW_E * ED * 128) * sizeof(float);    // 133,632
    const size_t smem_node = (size_t)(128 * 256 + 64 * 256 + 2 * 128 +
                                      NW_N * ND * 128) * sizeof(float);    // 230,400

    cudaFuncSetAttribute(pre_kernel,  cudaFuncAttributeMaxDynamicSharedMemorySize,
                         (int)smem_pre);
    cudaFuncSetAttribute(edge_kernel, cudaFuncAttributeMaxDynamicSharedMemorySize,
                         (int)smem_edge);
    cudaFuncSetAttribute(node_kernel, cudaFuncAttributeMaxDynamicSharedMemorySize,
                         (int)smem_node);

    zero_kernel<<<256, 256>>>(N);
    detect_kernel<<<16, 256>>>((const unsigned int*)ei, E);
    pre_kernel<<<nsm, TPB_P, smem_pre>>>(x, We1, N);
    edge_kernel<<<nsm, TPB_E, smem_edge>>>(pos,
                                           (const int*)ei, (const long long*)ei,
                                           eattr, s,
                                           We1, be1, We2, be2, Wc, bc, E, N);
    node_kernel<<<nsm, TPB_N, smem_node>>>(x, pos, Wn1, bn1, Wn2, bn2,
                                           xout, posout, N);
}

// round 15
// speedup vs baseline: 1.0591x; 1.0591x over previous
#include <cuda_runtime.h>
#include <cuda_bf16.h>
#include <cstdint>

// ---------------------------------------------------------------------------
// EGNN layer, fused, f32x2 (FFMA2) GEMV path + algebraic layer-1 hoisting
// + cp.async prefetch pipeline for the P/Q edge gather.
//   Layer 1 of the edge MLP is linear in the gathered features:
//     e_in @ W_e1 = x[dst]@W1a + x[src]@W1b + r2*w_r2 + ea*w_ea
//   P = x@W1a, Q = x@W1b precomputed per NODE (pre_kernel); per-EDGE layer 1
//   is silu(P[dst]+Q[src]+r2*w_r2+ea*w_ea+b1). edge_kernel runs the 128-deep
//   layer-2 GEMV + epilogue at ED=8 edges/warp, 12 warps/block (3/SMSP),
//   with P/Q for group i+1 prefetched via LDGSTS while group i's GEMV runs.
// Weights stored k-pair interleaved with a 16B XOR swizzle -> conflict-free
// warp-wide LDS.128; accumulation is k-pairwise in f32x2 lanes.
// ---------------------------------------------------------------------------

#define NMAX 50048

#define NW_P 8
#define TPB_P (NW_P * 32)   // 256
#define ND_P 8              // nodes per warp (pre)

#define NW_E 12
#define TPB_E (NW_E * 32)   // 384
#define ED 8                // edges per warp

#define NW_N 8
#define TPB_N (NW_N * 32)   // 256
#define ND 8                // nodes per warp

__device__ __align__(16) float g_msum[(size_t)NMAX * 128];
__device__ __align__(16) float g_coord[(size_t)NMAX * 3];
__device__ __align__(16) float g_deg[NMAX];
__device__ __align__(16) float g_P[(size_t)NMAX * 128];
__device__ __align__(16) float g_Q[(size_t)NMAX * 128];
__device__ int g_or;        // 0 => indices are int64, nonzero => int32

__device__ __forceinline__ float silu_f(float v) {
    return __fdividef(v, 1.0f + __expf(-v));
}

__device__ __forceinline__ void red_add_v4(float* addr, float4 v) {
    asm volatile("red.global.add.v4.f32 [%0], {%1,%2,%3,%4};"
                 :: "l"(addr), "f"(v.x), "f"(v.y), "f"(v.z), "f"(v.w)
                 : "memory");
}

__device__ __forceinline__ void fma2(unsigned long long& a,
                                     unsigned long long v,
                                     unsigned long long w) {
    asm("fma.rn.f32x2 %0, %1, %2, %0;" : "+l"(a) : "l"(v), "l"(w));
}
__device__ __forceinline__ float lohi_sum(unsigned long long a) {
    float lo, hi;
    asm("mov.b64 {%0,%1}, %2;" : "=f"(lo), "=f"(hi) : "l"(a));
    return lo + hi;
}

__device__ __forceinline__ uint32_t smem_u32(const void* p) {
    uint32_t a;
    asm("{ .reg .u64 t; cvta.to.shared.u64 t, %1; cvt.u32.u64 %0, t; }"
        : "=r"(a) : "l"(p));
    return a;
}
__device__ __forceinline__ void cp16(uint32_t dsts, const void* src) {
    asm volatile("cp.async.ca.shared.global [%0], [%1], 16;"
                 :: "r"(dsts), "l"(src) : "memory");
}
#define CP_COMMIT() asm volatile("cp.async.commit_group;" ::: "memory")
#define CP_WAIT0()  asm volatile("cp.async.wait_group 0;" ::: "memory")

// Swizzled index for k-pair interleaved weight storage (see earlier rounds).
// acc[g][i] ends up holding output j = lane*4 + i.
__device__ __forceinline__ int wswz(int k, int j) {
    int k2 = k >> 1, p = k & 1;
    int col = j * 2 + p;             // 0..255
    int L = col >> 3;                // owning lane
    int o = col & 7;
    int c = o >> 2;                  // chunk 0/1
    int pos = o & 3;
    return k2 * 256 + (L * 2 + (c ^ ((L >> 2) & 1))) * 4 + pos;
}

// One k4 step (2 k-pairs = 4 k values) of the packed GEMV for NA accumulators.
template<int NA>
__device__ __forceinline__ void gemv_step(const float* __restrict__ wrow,
                                          int s4,
                                          const float* __restrict__ act,
                                          int actStride, int kofs,
                                          unsigned long long (*acc)[4]) {
    ulonglong2 a0 = *(const ulonglong2*)(wrow + s4);
    ulonglong2 c0 = *(const ulonglong2*)(wrow + 4 - s4);
    ulonglong2 a1 = *(const ulonglong2*)(wrow + 256 + s4);
    ulonglong2 c1 = *(const ulonglong2*)(wrow + 256 + 4 - s4);
    #pragma unroll
    for (int g = 0; g < NA; g++) {
        ulonglong2 v = *(const ulonglong2*)(act + g * actStride + kofs);
        fma2(acc[g][0], v.x, a0.x); fma2(acc[g][1], v.x, a0.y);
        fma2(acc[g][2], v.x, c0.x); fma2(acc[g][3], v.x, c0.y);
        fma2(acc[g][0], v.y, a1.x); fma2(acc[g][1], v.y, a1.y);
        fma2(acc[g][2], v.y, c1.x); fma2(acc[g][3], v.y, c1.y);
    }
}

// ------------------------------- zero ---------------------------------------
__global__ void zero_kernel(int n) {
    int i = blockIdx.x * blockDim.x + threadIdx.x;
    int stride = gridDim.x * blockDim.x;
    if (i == 0) g_or = 0;
    int total = n * 128;
    for (int j = i; j < total; j += stride) g_msum[j] = 0.0f;
    for (int j = i; j < n * 3; j += stride) g_coord[j] = 0.0f;
    for (int j = i; j < n;     j += stride) g_deg[j]   = 0.0f;
}

// ------------------------------- detect --------------------------------------
__global__ void detect_kernel(const unsigned int* w, int E) {
    unsigned acc = 0;
    int lim = E < 8192 ? E : 8192;
    for (int i = blockIdx.x * blockDim.x + threadIdx.x; i < lim;
         i += gridDim.x * blockDim.x)
        acc |= w[2 * i + 1];
    if (acc) atomicOr(&g_or, 1);
}

// ------------------------------- pre ----------------------------------------
// P = x @ W1[0:128,:],  Q = x @ W1[128:256,:]   (no bias)
__global__ __launch_bounds__(TPB_P, 1)
void pre_kernel(const float* __restrict__ x, const float* __restrict__ We1,
                int N)
{
    extern __shared__ float sm[];
    float* sWa = sm;
    float* sWb = sWa + 64 * 256;
    float* sE  = sWb + 64 * 256;

    const int tid = threadIdx.x;
    for (int idx = tid; idx < 128 * 128; idx += TPB_P) {
        int k = idx >> 7, j = idx & 127;
        int d = wswz(k, j);
        sWa[d] = We1[idx];
        sWb[d] = We1[128 * 128 + idx];
    }
    __syncthreads();

    const int lane = tid & 31;
    const int w    = tid >> 5;
    float* eb = sE + w * (ND_P * 128);

    const int wofs = lane * 8;
    const int s4   = ((lane >> 2) & 1) * 4;

    const int bstride = gridDim.x * NW_P * ND_P;
    for (int b0 = (blockIdx.x * NW_P + w) * ND_P; b0 < N; b0 += bstride) {
        __syncwarp();
        #pragma unroll
        for (int g = 0; g < ND_P; g++) {
            int ng = b0 + g; if (ng >= N) ng = N - 1;
            *(float4*)(eb + g * 128 + lane * 4) =
                *(const float4*)(x + (size_t)ng * 128 + lane * 4);
        }
        __syncwarp();

        unsigned long long acc[ND_P][4];
        #pragma unroll
        for (int g = 0; g < ND_P; g++)
            acc[g][0] = acc[g][1] = acc[g][2] = acc[g][3] = 0ull;
        #pragma unroll 4
        for (int k4 = 0; k4 < 32; k4++)
            gemv_step<ND_P>(sWa + (k4 * 2) * 256 + wofs, s4, eb, 128, k4 * 4, acc);
        #pragma unroll
        for (int g = 0; g < ND_P; g++) {
            int ng = b0 + g;
            if (ng < N) {
                float4 o;
                o.x = lohi_sum(acc[g][0]); o.y = lohi_sum(acc[g][1]);
                o.z = lohi_sum(acc[g][2]); o.w = lohi_sum(acc[g][3]);
                *(float4*)(g_P + (size_t)ng * 128 + lane * 4) = o;
            }
            acc[g][0] = acc[g][1] = acc[g][2] = acc[g][3] = 0ull;
        }

        #pragma unroll 4
        for (int k4 = 0; k4 < 32; k4++)
            gemv_step<ND_P>(sWb + (k4 * 2) * 256 + wofs, s4, eb, 128, k4 * 4, acc);
        #pragma unroll
        for (int g = 0; g < ND_P; g++) {
            int ng = b0 + g;
            if (ng < N) {
                float4 o;
                o.x = lohi_sum(acc[g][0]); o.y = lohi_sum(acc[g][1]);
                o.z = lohi_sum(acc[g][2]); o.w = lohi_sum(acc[g][3]);
                *(float4*)(g_Q + (size_t)ng * 128 + lane * 4) = o;
            }
        }
    }
}

// ------------------------------- edge ---------------------------------------
// SMEM floats: sW2[64*256]=16384  consts[640]
//              eb[NW_E*ED*128]=12288  ebPQ[NW_E*ED*256]=24576
//              -> 53,888 floats = 215,552 B
__global__ __launch_bounds__(TPB_E, 1)
void edge_kernel(const float* __restrict__ pos,
                 const int* __restrict__ ei32, const long long* __restrict__ ei64,
                 const float* __restrict__ eattr, const float* __restrict__ s,
                 const float* __restrict__ We1, const float* __restrict__ be1,
                 const float* __restrict__ We2, const float* __restrict__ be2,
                 const float* __restrict__ Wc,  const float* __restrict__ bc,
                 int E, int Nn)
{
    extern __shared__ float sm[];
    float* sW2 = sm;                  // 64 k2-rows x 256
    float* sWc = sW2 + 64 * 256;
    float* sb2 = sWc + 128;
    float* sb1 = sb2 + 128;
    float* swr = sb1 + 128;           // W1 row 256 (r2 weights)
    float* swe = swr + 128;           // W1 row 257 (edge_attr weights)
    float* sE  = swe + 128;           // eb: NW_E*ED*128
    float* sPQ = sE + NW_E * ED * 128;// ebPQ: NW_E*ED*256

    const int tid = threadIdx.x;
    for (int idx = tid; idx < 128 * 128; idx += TPB_E) {
        int k = idx >> 7, j = idx & 127;
        sW2[wswz(k, j)] = We2[idx];
    }
    for (int i = tid; i < 128; i += TPB_E) {
        sWc[i] = Wc[i]; sb2[i] = be2[i]; sb1[i] = be1[i];
        swr[i] = We1[256 * 128 + i];
        swe[i] = We1[257 * 128 + i];
    }
    __syncthreads();

    const bool idx64 = (g_or == 0);
    const float bcv  = bc[0];
    const int lane   = tid & 31;
    const int w      = tid >> 5;
    float* eb   = sE  + w * (ED * 128);
    float* ebPQ = sPQ + w * (ED * 256);
    const uint32_t pqs = smem_u32(ebPQ);

    const int wofs = lane * 8;
    const int s4   = ((lane >> 2) & 1) * 4;

    const long long bstride = (long long)gridDim.x * NW_E * ED;
    long long b0 = ((long long)blockIdx.x * NW_E + w) * ED;

    // ---- current-group metadata (lane g owns edge b0+g) ----
    int   ss = 0, dd = 0;
    bool  have = false;
    float dx = 0.f, dy = 0.f, dz = 0.f, r2 = 0.f, ea = 0.f, sg = 0.f;

    // prologue: load meta + prefetch PQ for first group
    if (b0 < E) {
        long long e = b0 + lane;
        have = (lane < ED) && (e < (long long)E);
        if (have) {
            if (idx64) { ss = (int)ei64[e]; dd = (int)ei64[E + e]; }
            else       { ss = ei32[e];      dd = ei32[E + e]; }
            if ((unsigned)ss >= (unsigned)Nn || (unsigned)dd >= (unsigned)Nn) {
                have = false; ss = 0; dd = 0;
            }
        }
        if (lane < ED) {
            dx = pos[dd * 3 + 0] - pos[ss * 3 + 0];
            dy = pos[dd * 3 + 1] - pos[ss * 3 + 1];
            dz = pos[dd * 3 + 2] - pos[ss * 3 + 2];
            r2 = dx * dx + dy * dy + dz * dz;
            ea = have ? eattr[e] : 0.0f;
            sg = s[ss];
        }
        #pragma unroll
        for (int g = 0; g < ED; g++) {
            int dg  = __shfl_sync(0xffffffffu, dd, g);
            int sgi = __shfl_sync(0xffffffffu, ss, g);
            cp16(pqs + (uint32_t)(g * 256 + lane * 4) * 4,
                 g_P + (size_t)dg * 128 + lane * 4);
            cp16(pqs + (uint32_t)(g * 256 + 128 + lane * 4) * 4,
                 g_Q + (size_t)sgi * 128 + lane * 4);
        }
        CP_COMMIT();
    }

    for (; b0 < E; b0 += bstride) {
        const long long b1 = b0 + bstride;

        // ---- wait for this group's P/Q (each lane consumes its own chunks) --
        CP_WAIT0();

        // ---- layer-1 via hoisting: h = silu(P[dst]+Q[src]+r2*wr+ea*we+b1) ---
        {
            const float4 wrv  = *(const float4*)(swr + lane * 4);
            const float4 wev  = *(const float4*)(swe + lane * 4);
            const float4 sb1v = *(const float4*)(sb1 + lane * 4);
            #pragma unroll
            for (int g = 0; g < ED; g++) {
                float r2g = __shfl_sync(0xffffffffu, r2, g);
                float eag = __shfl_sync(0xffffffffu, ea, g);
                float4 pv = *(const float4*)(ebPQ + g * 256 + lane * 4);
                float4 qv = *(const float4*)(ebPQ + g * 256 + 128 + lane * 4);
                float4 h;
                h.x = silu_f(fmaf(r2g, wrv.x, fmaf(eag, wev.x, pv.x + qv.x + sb1v.x)));
                h.y = silu_f(fmaf(r2g, wrv.y, fmaf(eag, wev.y, pv.y + qv.y + sb1v.y)));
                h.z = silu_f(fmaf(r2g, wrv.z, fmaf(eag, wev.z, pv.z + qv.z + sb1v.z)));
                h.w = silu_f(fmaf(r2g, wrv.w, fmaf(eag, wev.w, pv.w + qv.w + sb1v.w)));
                *(float4*)(eb + g * 128 + lane * 4) = h;
            }
        }
        __syncwarp();   // h visible to all lanes before GEMV

        // ---- load next-group metadata and prefetch its P/Q -----------------
        int   ss_n = 0, dd_n = 0;
        bool  have_n = false;
        float dx_n = 0.f, dy_n = 0.f, dz_n = 0.f, r2_n = 0.f, ea_n = 0.f, sg_n = 0.f;
        if (b1 < E) {
            long long e = b1 + lane;
            have_n = (lane < ED) && (e < (long long)E);
            if (have_n) {
                if (idx64) { ss_n = (int)ei64[e]; dd_n = (int)ei64[E + e]; }
                else       { ss_n = ei32[e];      dd_n = ei32[E + e]; }
                if ((unsigned)ss_n >= (unsigned)Nn || (unsigned)dd_n >= (unsigned)Nn) {
                    have_n = false; ss_n = 0; dd_n = 0;
                }
            }
            if (lane < ED) {
                dx_n = pos[dd_n * 3 + 0] - pos[ss_n * 3 + 0];
                dy_n = pos[dd_n * 3 + 1] - pos[ss_n * 3 + 1];
                dz_n = pos[dd_n * 3 + 2] - pos[ss_n * 3 + 2];
                r2_n = dx_n * dx_n + dy_n * dy_n + dz_n * dz_n;
                ea_n = have_n ? eattr[e] : 0.0f;
                sg_n = s[ss_n];
            }
            #pragma unroll
            for (int g = 0; g < ED; g++) {
                int dg  = __shfl_sync(0xffffffffu, dd_n, g);
                int sgi = __shfl_sync(0xffffffffu, ss_n, g);
                cp16(pqs + (uint32_t)(g * 256 + lane * 4) * 4,
                     g_P + (size_t)dg * 128 + lane * 4);
                cp16(pqs + (uint32_t)(g * 256 + 128 + lane * 4) * 4,
                     g_Q + (size_t)sgi * 128 + lane * 4);
            }
            CP_COMMIT();
        }

        // ---- layer 2: 128 -> 128, f32x2 (covers the prefetch latency) ------
        unsigned long long acc[ED][4];
        #pragma unroll
        for (int g = 0; g < ED; g++)
            acc[g][0] = acc[g][1] = acc[g][2] = acc[g][3] = 0ull;
        #pragma unroll 4
        for (int k4 = 0; k4 < 32; k4++)
            gemv_step<ED>(sW2 + (k4 * 2) * 256 + wofs, s4, eb, 128, k4 * 4, acc);

        // ---- epilogue: SiLU, s-gate, gamma, scatter ------------------------
        {
            const float4 sb2v = *(const float4*)(sb2 + lane * 4);
            const float4 wcv  = *(const float4*)(sWc + lane * 4);
            const int okflag = have ? 1 : 0;
            float psel = 0.0f;
            #pragma unroll
            for (int g = 0; g < ED; g++) {
                float sgg = __shfl_sync(0xffffffffu, sg, g);
                float4 mg;
                mg.x = silu_f(lohi_sum(acc[g][0]) + sb2v.x) * sgg;
                mg.y = silu_f(lohi_sum(acc[g][1]) + sb2v.y) * sgg;
                mg.z = silu_f(lohi_sum(acc[g][2]) + sb2v.z) * sgg;
                mg.w = silu_f(lohi_sum(acc[g][3]) + sb2v.w) * sgg;

                float p = mg.x * wcv.x + mg.y * wcv.y + mg.z * wcv.z + mg.w * wcv.w;
                #pragma unroll
                for (int o = 16; o; o >>= 1)
                    p += __shfl_xor_sync(0xffffffffu, p, o);

                int okg = __shfl_sync(0xffffffffu, okflag, g);
                int dg  = __shfl_sync(0xffffffffu, dd, g);
                if (okg) red_add_v4(g_msum + (size_t)dg * 128 + lane * 4, mg);
                if (lane == g) psel = p;
            }
            if (lane < ED && have) {
                const float gam = psel + bcv;
                atomicAdd(g_coord + dd * 3 + 0, gam * dx);
                atomicAdd(g_coord + dd * 3 + 1, gam * dy);
                atomicAdd(g_coord + dd * 3 + 2, gam * dz);
                atomicAdd(g_deg + dd, 1.0f);
            }
        }

        // ---- rotate next -> current ----------------------------------------
        ss = ss_n; dd = dd_n; have = have_n;
        dx = dx_n; dy = dy_n; dz = dz_n; r2 = r2_n; ea = ea_n; sg = sg_n;
        __syncwarp();   // eb fully consumed before next group's h overwrite
    }
}

// ------------------------------- node ---------------------------------------
// SMEM floats: sWn1[128*256]=32768  sWn2[64*256]=16384  biases 256
//              sE[NW_N*ND*128]=8192  -> 57600 floats = 230,400 B
__global__ __launch_bounds__(TPB_N, 1)
void node_kernel(const float* __restrict__ x, const float* __restrict__ pos,
                 const float* __restrict__ Wn1, const float* __restrict__ bn1,
                 const float* __restrict__ Wn2, const float* __restrict__ bn2,
                 float* __restrict__ xout, float* __restrict__ posout,
                 int N)
{
    extern __shared__ float sm[];
    float* sW1 = sm;                  // 128 k2-rows x 256
    float* sW2 = sW1 + 128 * 256;     // 64 k2-rows x 256
    float* sb1 = sW2 + 64 * 256;
    float* sb2 = sb1 + 128;
    float* sE  = sb2 + 128;

    const int tid = threadIdx.x;
    for (int idx = tid; idx < 256 * 128; idx += TPB_N) {
        int k = idx >> 7, j = idx & 127;
        sW1[wswz(k, j)] = Wn1[idx];
    }
    for (int idx = tid; idx < 128 * 128; idx += TPB_N) {
        int k = idx >> 7, j = idx & 127;
        sW2[wswz(k, j)] = Wn2[idx];
    }
    for (int i = tid; i < 128; i += TPB_N) { sb1[i] = bn1[i]; sb2[i] = bn2[i]; }
    __syncthreads();

    const int lane = tid & 31;
    const int w    = tid >> 5;
    float* eb = sE + w * (ND * 128);

    const int wofs = lane * 8;
    const int s4   = ((lane >> 2) & 1) * 4;
    const float4 sb1v = *(const float4*)(sb1 + lane * 4);
    const float4 sb2v = *(const float4*)(sb2 + lane * 4);

    const int bstride = gridDim.x * NW_N * ND;
    for (int b0 = (blockIdx.x * NW_N + w) * ND; b0 < N; b0 += bstride) {

        int nm = b0 + lane;
        float inv = 1.0f;
        if (lane < ND && nm < N) inv = 1.0f / fmaxf(g_deg[nm], 1.0f);

        unsigned long long acc[ND][4];
        #pragma unroll
        for (int g = 0; g < ND; g++)
            acc[g][0] = acc[g][1] = acc[g][2] = acc[g][3] = 0ull;

        // ---- layer 1 phase A: rows 0..127 with x ----
        __syncwarp();
        #pragma unroll
        for (int g = 0; g < ND; g++) {
            int ng = b0 + g; if (ng >= N) ng = N - 1;
            *(float4*)(eb + g * 128 + lane * 4) =
                *(const float4*)(x + (size_t)ng * 128 + lane * 4);
        }
        __syncwarp();
        #pragma unroll 4
        for (int k4 = 0; k4 < 32; k4++)
            gemv_step<ND>(sW1 + (k4 * 2) * 256 + wofs, s4, eb, 128, k4 * 4, acc);

        // ---- layer 1 phase B: rows 128..255 with m_sum/deg ----
        __syncwarp();
        #pragma unroll
        for (int g = 0; g < ND; g++) {
            int ng = b0 + g; if (ng >= N) ng = N - 1;
            float ig = __shfl_sync(0xffffffffu, inv, g);
            float4 ms = *(const float4*)(g_msum + (size_t)ng * 128 + lane * 4);
            ms.x *= ig; ms.y *= ig; ms.z *= ig; ms.w *= ig;
            *(float4*)(eb + g * 128 + lane * 4) = ms;
        }
        __syncwarp();
        #pragma unroll 4
        for (int k4 = 0; k4 < 32; k4++)
            gemv_step<ND>(sW1 + ((k4 + 32) * 2) * 256 + wofs, s4, eb, 128, k4 * 4, acc);

        // ---- SiLU, stage h, layer 2 ----
        __syncwarp();
        #pragma unroll
        for (int g = 0; g < ND; g++) {
            float4 h;
            h.x = silu_f(lohi_sum(acc[g][0]) + sb1v.x);
            h.y = silu_f(lohi_sum(acc[g][1]) + sb1v.y);
            h.z = silu_f(lohi_sum(acc[g][2]) + sb1v.z);
            h.w = silu_f(lohi_sum(acc[g][3]) + sb1v.w);
            *(float4*)(eb + g * 128 + lane * 4) = h;
            acc[g][0] = acc[g][1] = acc[g][2] = acc[g][3] = 0ull;
        }
        __syncwarp();

        #pragma unroll 4
        for (int k4 = 0; k4 < 32; k4++)
            gemv_step<ND>(sW2 + (k4 * 2) * 256 + wofs, s4, eb, 128, k4 * 4, acc);

        #pragma unroll
        for (int g = 0; g < ND; g++) {
            int ng = b0 + g;
            if (ng < N) {
                float4 o;
                o.x = lohi_sum(acc[g][0]) + sb2v.x;
                o.y = lohi_sum(acc[g][1]) + sb2v.y;
                o.z = lohi_sum(acc[g][2]) + sb2v.z;
                o.w = lohi_sum(acc[g][3]) + sb2v.w;
                *(float4*)(xout + (size_t)ng * 128 + lane * 4) = o;
                float ig = __shfl_sync(0xffffffffu, inv, g);
                if (lane < 3)
                    posout[ng * 3 + lane] =
                        pos[ng * 3 + lane] + g_coord[ng * 3 + lane] * ig;
            }
        }
    }
}

// ------------------------------- launch --------------------------------------
extern "C" void kernel_launch(void* const* d_in, const int* in_sizes, int n_in,
                              void* d_out, int out_size) {
    const float* x     = (const float*)d_in[0];
    const float* pos   = (const float*)d_in[1];
    const void*  ei    = d_in[2];
    const float* eattr = (const float*)d_in[3];
    const float* s     = (const float*)d_in[4];
    const float* We1   = (const float*)d_in[5];
    const float* be1   = (const float*)d_in[6];
    const float* We2   = (const float*)d_in[7];
    const float* be2   = (const float*)d_in[8];
    const float* Wn1   = (const float*)d_in[9];
    const float* bn1   = (const float*)d_in[10];
    const float* Wn2   = (const float*)d_in[11];
    const float* bn2   = (const float*)d_in[12];
    const float* Wc    = (const float*)d_in[13];
    const float* bc    = (const float*)d_in[14];

    const int N = in_sizes[0] / 128;
    const int E = in_sizes[2] / 2;

    float* xout   = (float*)d_out;
    float* posout = (float*)d_out + (size_t)N * 128;

    int dev = 0, nsm = 148;
    cudaGetDevice(&dev);
    cudaDeviceGetAttribute(&nsm, cudaDevAttrMultiProcessorCount, dev);

    const size_t smem_pre  = (size_t)(64 * 256 + 64 * 256 +
                                      NW_P * ND_P * 128) * sizeof(float);  // 163,840
    const size_t smem_edge = (size_t)(64 * 256 + 5 * 128 +
                                      NW_E * ED * 128 +
                                      NW_E * ED * 256) * sizeof(float);    // 215,552
    const size_t smem_node = (size_t)(128 * 256 + 64 * 256 + 2 * 128 +
                                      NW_N * ND * 128) * sizeof(float);    // 230,400

    cudaFuncSetAttribute(pre_kernel,  cudaFuncAttributeMaxDynamicSharedMemorySize,
                         (int)smem_pre);
    cudaFuncSetAttribute(edge_kernel, cudaFuncAttributeMaxDynamicSharedMemorySize,
                         (int)smem_edge);
    cudaFuncSetAttribute(node_kernel, cudaFuncAttributeMaxDynamicSharedMemorySize,
                         (int)smem_node);

    zero_kernel<<<512, 256>>>(N);
    detect_kernel<<<16, 256>>>((const unsigned int*)ei, E);
    pre_kernel<<<nsm, TPB_P, smem_pre>>>(x, We1, N);
    edge_kernel<<<nsm, TPB_E, smem_edge>>>(pos,
                                           (const int*)ei, (const long long*)ei,
                                           eattr, s,
                                           We1, be1, We2, be2, Wc, bc, E, N);
    node_kernel<<<nsm, TPB_N, smem_node>>>(x, pos, Wn1, bn1, Wn2, bn2,
                                           xout, posout, N);
}

// round 17
// speedup vs baseline: 1.1384x; 1.0749x over previous
#include <cuda_runtime.h>
#include <cuda_bf16.h>
#include <cstdint>

// ---------------------------------------------------------------------------
// EGNN layer: layer-1 hoisting (P/Q per node) + mma.sync (HMMA bf16) hi/lo
// tensor-core path for the edge layer-2 GEMM (plain sm_103 compatible —
// tcgen05 is rejected by this harness's sm_103 target).
//   pre_kernel:  P = x@W1a, Q = x@W1b  (f32x2 FFMA2 GEMV)
//   edge_kernel: per 128-edge tile:
//     meta -> h = silu(P[dst]+Q[src]+r2*wr+ea*we+b1) -> bf16 hi/lo A tiles
//     -> mma.sync m16n8k16: D = Ah*Bh + Ah*Bl + Al*Bh (f32 regs)
//     -> D to SMEM -> row-major epilogue: silu+gate+gamma+scatter.
//   node_kernel: f32x2 GEMV node MLP (unchanged, proven).
// ---------------------------------------------------------------------------

#define NMAX 50048

#define NW_P 8
#define TPB_P (NW_P * 32)   // 256
#define ND_P 8

#define TPB_E 256           // 8 warps: 4 M-strips x 2 N-halves

#define NW_N 8
#define TPB_N (NW_N * 32)   // 256
#define ND 8

__device__ __align__(16) float g_msum[(size_t)NMAX * 128];
__device__ __align__(16) float g_coord[(size_t)NMAX * 3];
__device__ __align__(16) float g_deg[NMAX];
__device__ __align__(16) float g_P[(size_t)NMAX * 128];
__device__ __align__(16) float g_Q[(size_t)NMAX * 128];
__device__ int g_or;        // 0 => indices are int64, nonzero => int32

__device__ __forceinline__ float silu_f(float v) {
    return __fdividef(v, 1.0f + __expf(-v));
}

__device__ __forceinline__ void red_add_v4(float* addr, float4 v) {
    asm volatile("red.global.add.v4.f32 [%0], {%1,%2,%3,%4};"
                 :: "l"(addr), "f"(v.x), "f"(v.y), "f"(v.z), "f"(v.w)
                 : "memory");
}

__device__ __forceinline__ void fma2(unsigned long long& a,
                                     unsigned long long v,
                                     unsigned long long w) {
    asm("fma.rn.f32x2 %0, %1, %2, %0;" : "+l"(a) : "l"(v), "l"(w));
}
__device__ __forceinline__ float lohi_sum(unsigned long long a) {
    float lo, hi;
    asm("mov.b64 {%0,%1}, %2;" : "=f"(lo), "=f"(hi) : "l"(a));
    return lo + hi;
}
__device__ __forceinline__ uint32_t smem_u32(const void* p) {
    uint32_t a;
    asm("{ .reg .u64 t; cvta.to.shared.u64 t, %1; cvt.u32.u64 %0, t; }"
        : "=r"(a) : "l"(p));
    return a;
}

// f32x2 GEMV weight swizzle (pre/node kernels)
__device__ __forceinline__ int wswz(int k, int j) {
    int k2 = k >> 1, p = k & 1;
    int col = j * 2 + p;
    int L = col >> 3;
    int o = col & 7;
    int c = o >> 2;
    int pos = o & 3;
    return k2 * 256 + (L * 2 + (c ^ ((L >> 2) & 1))) * 4 + pos;
}

template<int NA>
__device__ __forceinline__ void gemv_step(const float* __restrict__ wrow,
                                          int s4,
                                          const float* __restrict__ act,
                                          int actStride, int kofs,
                                          unsigned long long (*acc)[4]) {
    ulonglong2 a0 = *(const ulonglong2*)(wrow + s4);
    ulonglong2 c0 = *(const ulonglong2*)(wrow + 4 - s4);
    ulonglong2 a1 = *(const ulonglong2*)(wrow + 256 + s4);
    ulonglong2 c1 = *(const ulonglong2*)(wrow + 256 + 4 - s4);
    #pragma unroll
    for (int g = 0; g < NA; g++) {
        ulonglong2 v = *(const ulonglong2*)(act + g * actStride + kofs);
        fma2(acc[g][0], v.x, a0.x); fma2(acc[g][1], v.x, a0.y);
        fma2(acc[g][2], v.x, c0.x); fma2(acc[g][3], v.x, c0.y);
        fma2(acc[g][0], v.y, a1.x); fma2(acc[g][1], v.y, a1.y);
        fma2(acc[g][2], v.y, c1.x); fma2(acc[g][3], v.y, c1.y);
    }
}

// ---------------- mma.sync helpers (edge kernel) -----------------------------

// bf16 tile [128 rows][128 cols], row stride 256B, 16B-chunk XOR swizzle.
__device__ __forceinline__ uint32_t sw_bf16(int row, int col) {
    int chunk = (col >> 3) ^ (row & 7);
    return (uint32_t)(row * 256 + chunk * 16 + (col & 7) * 2);
}
// f32 tile [128 rows][128 cols], row stride 512B, 16B-chunk XOR swizzle.
__device__ __forceinline__ uint32_t sw_f32(int row, int col) {
    int chunk = (col >> 2) ^ (row & 7);
    return (uint32_t)(row * 512 + chunk * 16 + (col & 3) * 4);
}

__device__ __forceinline__ void ldsm4(uint32_t* r, uint32_t addr) {
    asm volatile("ldmatrix.sync.aligned.m8n8.x4.shared.b16 {%0,%1,%2,%3}, [%4];"
                 : "=r"(r[0]), "=r"(r[1]), "=r"(r[2]), "=r"(r[3]) : "r"(addr));
}

__device__ __forceinline__ void mma_bf16(float* d, const uint32_t* a,
                                         const uint32_t* b) {
    asm volatile(
        "mma.sync.aligned.m16n8k16.row.col.f32.bf16.bf16.f32 "
        "{%0,%1,%2,%3}, {%4,%5,%6,%7}, {%8,%9}, {%0,%1,%2,%3};"
        : "+f"(d[0]), "+f"(d[1]), "+f"(d[2]), "+f"(d[3])
        : "r"(a[0]), "r"(a[1]), "r"(a[2]), "r"(a[3]), "r"(b[0]), "r"(b[1]));
}

// ------------------------------- zero ---------------------------------------
__global__ void zero_kernel(int n) {
    int i = blockIdx.x * blockDim.x + threadIdx.x;
    int stride = gridDim.x * blockDim.x;
    if (i == 0) g_or = 0;
    int total = n * 128;
    for (int j = i; j < total; j += stride) g_msum[j] = 0.0f;
    for (int j = i; j < n * 3; j += stride) g_coord[j] = 0.0f;
    for (int j = i; j < n;     j += stride) g_deg[j]   = 0.0f;
}

// ------------------------------- detect --------------------------------------
__global__ void detect_kernel(const unsigned int* w, int E) {
    unsigned acc = 0;
    int lim = E < 8192 ? E : 8192;
    for (int i = blockIdx.x * blockDim.x + threadIdx.x; i < lim;
         i += gridDim.x * blockDim.x)
        acc |= w[2 * i + 1];
    if (acc) atomicOr(&g_or, 1);
}

// ------------------------------- pre ----------------------------------------
__global__ __launch_bounds__(TPB_P, 1)
void pre_kernel(const float* __restrict__ x, const float* __restrict__ We1,
                int N)
{
    extern __shared__ float sm[];
    float* sWa = sm;
    float* sWb = sWa + 64 * 256;
    float* sE  = sWb + 64 * 256;

    const int tid = threadIdx.x;
    for (int idx = tid; idx < 128 * 128; idx += TPB_P) {
        int k = idx >> 7, j = idx & 127;
        int d = wswz(k, j);
        sWa[d] = We1[idx];
        sWb[d] = We1[128 * 128 + idx];
    }
    __syncthreads();

    const int lane = tid & 31;
    const int w    = tid >> 5;
    float* eb = sE + w * (ND_P * 128);

    const int wofs = lane * 8;
    const int s4   = ((lane >> 2) & 1) * 4;

    const int bstride = gridDim.x * NW_P * ND_P;
    for (int b0 = (blockIdx.x * NW_P + w) * ND_P; b0 < N; b0 += bstride) {
        __syncwarp();
        #pragma unroll
        for (int g = 0; g < ND_P; g++) {
            int ng = b0 + g; if (ng >= N) ng = N - 1;
            *(float4*)(eb + g * 128 + lane * 4) =
                *(const float4*)(x + (size_t)ng * 128 + lane * 4);
        }
        __syncwarp();

        unsigned long long acc[ND_P][4];
        #pragma unroll
        for (int g = 0; g < ND_P; g++)
            acc[g][0] = acc[g][1] = acc[g][2] = acc[g][3] = 0ull;
        #pragma unroll 4
        for (int k4 = 0; k4 < 32; k4++)
            gemv_step<ND_P>(sWa + (k4 * 2) * 256 + wofs, s4, eb, 128, k4 * 4, acc);
        #pragma unroll
        for (int g = 0; g < ND_P; g++) {
            int ng = b0 + g;
            if (ng < N) {
                float4 o;
                o.x = lohi_sum(acc[g][0]); o.y = lohi_sum(acc[g][1]);
                o.z = lohi_sum(acc[g][2]); o.w = lohi_sum(acc[g][3]);
                *(float4*)(g_P + (size_t)ng * 128 + lane * 4) = o;
            }
            acc[g][0] = acc[g][1] = acc[g][2] = acc[g][3] = 0ull;
        }

        #pragma unroll 4
        for (int k4 = 0; k4 < 32; k4++)
            gemv_step<ND_P>(sWb + (k4 * 2) * 256 + wofs, s4, eb, 128, k4 * 4, acc);
        #pragma unroll
        for (int g = 0; g < ND_P; g++) {
            int ng = b0 + g;
            if (ng < N) {
                float4 o;
                o.x = lohi_sum(acc[g][0]); o.y = lohi_sum(acc[g][1]);
                o.z = lohi_sum(acc[g][2]); o.w = lohi_sum(acc[g][3]);
                *(float4*)(g_Q + (size_t)ng * 128 + lane * 4) = o;
            }
        }
    }
}

// ------------------------------- edge (mma.sync) -----------------------------
// SMEM bytes: Bh 32768 | Bl 32768 | A (Ah 32768 + Al 32768; D f32 overlays) |
//             meta: 11 float[128] + 3 int[128] = 7168   -> 138,240 B
__global__ __launch_bounds__(TPB_E, 1)
void edge_kernel(const float* __restrict__ pos,
                 const int* __restrict__ ei32, const long long* __restrict__ ei64,
                 const float* __restrict__ eattr, const float* __restrict__ s,
                 const float* __restrict__ We1, const float* __restrict__ be1,
                 const float* __restrict__ We2, const float* __restrict__ be2,
                 const float* __restrict__ Wc,  const float* __restrict__ bc,
                 int E, int Nn)
{
    extern __shared__ __align__(1024) char smraw[];
    char* sBh = smraw;                 // W2^T hi
    char* sBl = smraw + 32768;         // W2^T lo
    char* sAh = smraw + 65536;         // h hi    (D f32 overlays sAh..+64K)
    char* sAl = smraw + 98304;         // h lo
    char* sD  = smraw + 65536;
    float* swr = (float*)(smraw + 131072);
    float* swe = swr + 128;
    float* sb1 = swe + 128;
    float* sb2 = sb1 + 128;
    float* swc = sb2 + 128;
    float* sr2 = swc + 128;
    float* sea = sr2 + 128;
    float* ssg = sea + 128;
    float* sdx = ssg + 128;
    float* sdy = sdx + 128;
    float* sdz = sdy + 128;
    int*   sdd = (int*)(sdz + 128);
    int*   sss = sdd + 128;
    int*   shv = sss + 128;

    const int tid  = threadIdx.x;
    const int wid  = tid >> 5;
    const int lane = tid & 31;
    const int warpM = wid & 3;          // 4 M-strips of 32 rows
    const int warpN = wid >> 2;         // 2 N-halves of 64 cols
    const uint32_t uAh = smem_u32(sAh);
    const uint32_t uAl = smem_u32(sAl);
    const uint32_t uBh = smem_u32(sBh);
    const uint32_t uBl = smem_u32(sBl);

    // stage constants + B tiles (hi/lo of W2^T: B[n][k] = W2[k][n])
    for (int i = tid; i < 128; i += TPB_E) {
        swr[i] = We1[256 * 128 + i];
        swe[i] = We1[257 * 128 + i];
        sb1[i] = be1[i];
        sb2[i] = be2[i];
        swc[i] = Wc[i];
    }
    for (int idx = tid; idx < 16384; idx += TPB_E) {
        int n = idx >> 7, k = idx & 127;
        float v = We2[k * 128 + n];
        __nv_bfloat16 hb = __float2bfloat16(v);
        float lo = v - __bfloat162float(hb);
        uint32_t o = sw_bf16(n, k);
        *(__nv_bfloat16*)(sBh + o) = hb;
        *(__nv_bfloat16*)(sBl + o) = __float2bfloat16(lo);
    }
    __syncthreads();

    const bool idx64 = (g_or == 0);
    const float bcv  = bc[0];

    const float4 wrv = *(const float4*)(swr + lane * 4);
    const float4 wev = *(const float4*)(swe + lane * 4);
    const float4 b1v = *(const float4*)(sb1 + lane * 4);
    const float4 b2v = *(const float4*)(sb2 + lane * 4);
    const float4 wcv = *(const float4*)(swc + lane * 4);

    // ldmatrix lane-address precompute
    // A (per strip ss): row = warpM*32 + ss*16 + (lane&7) + ((lane>>3)&1)*8
    //                   k-chunk = kk*2 + (lane>>4)
    int rA0 = warpM * 32 + (lane & 7) + ((lane >> 3) & 1) * 8;   // strip 0
    int rA1 = rA0 + 16;                                          // strip 1
    const int cA = (lane >> 4);           // k-chunk sub-index
    // B (per n-tile pair p): row = warpN*64 + p*16 + ((lane>>4)&1)*8 + (lane&7)
    //                        k-chunk = kk*2 + ((lane>>3)&1)
    int rB[4];
    #pragma unroll
    for (int p = 0; p < 4; p++)
        rB[p] = warpN * 64 + p * 16 + ((lane >> 4) & 1) * 8 + (lane & 7);
    const int cB = (lane >> 3) & 1;

    const int ntiles = (E + 127) >> 7;
    for (int t = blockIdx.x; t < ntiles; t += gridDim.x) {
        const long long base = (long long)t << 7;

        // ---- meta (threads 0..127 own one edge each) -----------------------
        if (tid < 128) {
            long long e = base + tid;
            int ok = (e < (long long)E) ? 1 : 0;
            int ssv = 0, ddv = 0;
            if (ok) {
                if (idx64) { ssv = (int)ei64[e]; ddv = (int)ei64[E + e]; }
                else       { ssv = ei32[e];      ddv = ei32[E + e]; }
                if ((unsigned)ssv >= (unsigned)Nn || (unsigned)ddv >= (unsigned)Nn) {
                    ok = 0; ssv = 0; ddv = 0;
                }
            }
            float dxv = 0.f, dyv = 0.f, dzv = 0.f, r2v = 0.f, eav = 0.f, sgv = 0.f;
            if (ok) {
                dxv = pos[ddv * 3 + 0] - pos[ssv * 3 + 0];
                dyv = pos[ddv * 3 + 1] - pos[ssv * 3 + 1];
                dzv = pos[ddv * 3 + 2] - pos[ssv * 3 + 2];
                r2v = dxv * dxv + dyv * dyv + dzv * dzv;
                eav = eattr[e];
                sgv = s[ssv];
            }
            sdd[tid] = ddv; sss[tid] = ssv; shv[tid] = ok;
            sr2[tid] = r2v; sea[tid] = eav; ssg[tid] = sgv;
            sdx[tid] = dxv; sdy[tid] = dyv; sdz[tid] = dzv;
        }
        __syncthreads();

        // ---- convert: h -> bf16 hi/lo A tiles (warp w: rows w*16..+15) -----
        #pragma unroll 4
        for (int g = 0; g < 16; g++) {
            int row = wid * 16 + g;
            int ddv = sdd[row], ssv = sss[row];
            float r2v = sr2[row], eav = sea[row];
            float4 pv = *(const float4*)(g_P + (size_t)ddv * 128 + lane * 4);
            float4 qv = *(const float4*)(g_Q + (size_t)ssv * 128 + lane * 4);
            float hx = silu_f(fmaf(r2v, wrv.x, fmaf(eav, wev.x, pv.x + qv.x + b1v.x)));
            float hy = silu_f(fmaf(r2v, wrv.y, fmaf(eav, wev.y, pv.y + qv.y + b1v.y)));
            float hz = silu_f(fmaf(r2v, wrv.z, fmaf(eav, wev.z, pv.z + qv.z + b1v.z)));
            float hw = silu_f(fmaf(r2v, wrv.w, fmaf(eav, wev.w, pv.w + qv.w + b1v.w)));
            __nv_bfloat16 bx = __float2bfloat16(hx);
            __nv_bfloat16 by = __float2bfloat16(hy);
            __nv_bfloat16 bz = __float2bfloat16(hz);
            __nv_bfloat16 bw = __float2bfloat16(hw);
            uint32_t h01 = (uint32_t)__bfloat16_as_ushort(bx)
                         | ((uint32_t)__bfloat16_as_ushort(by) << 16);
            uint32_t h23 = (uint32_t)__bfloat16_as_ushort(bz)
                         | ((uint32_t)__bfloat16_as_ushort(bw) << 16);
            uint32_t l01 = (uint32_t)__bfloat16_as_ushort(__float2bfloat16(hx - __bfloat162float(bx)))
                         | ((uint32_t)__bfloat16_as_ushort(__float2bfloat16(hy - __bfloat162float(by))) << 16);
            uint32_t l23 = (uint32_t)__bfloat16_as_ushort(__float2bfloat16(hz - __bfloat162float(bz)))
                         | ((uint32_t)__bfloat16_as_ushort(__float2bfloat16(hw - __bfloat162float(bw))) << 16);
            uint32_t o = (uint32_t)(row * 256 + (((lane >> 1) ^ (row & 7)) << 4)
                                    + (lane & 1) * 8);
            *(uint2*)(sAh + o) = make_uint2(h01, h23);
            *(uint2*)(sAl + o) = make_uint2(l01, l23);
        }
        __syncthreads();

        // ---- mma: D = Ah*Bh + Ah*Bl + Al*Bh (f32 fragment accum) -----------
        float acc[2][8][4];
        #pragma unroll
        for (int ss = 0; ss < 2; ss++)
            #pragma unroll
            for (int j = 0; j < 8; j++)
                #pragma unroll
                for (int q = 0; q < 4; q++) acc[ss][j][q] = 0.0f;

        #pragma unroll 1
        for (int kk = 0; kk < 8; kk++) {
            uint32_t ah[2][4], al[2][4];
            {
                uint32_t ch = (uint32_t)((kk * 2 + cA) ^ (rA0 & 7)) << 4;
                ldsm4(ah[0], uAh + rA0 * 256 + ch);
                ldsm4(al[0], uAl + rA0 * 256 + ch);
                uint32_t ch1 = (uint32_t)((kk * 2 + cA) ^ (rA1 & 7)) << 4;
                ldsm4(ah[1], uAh + rA1 * 256 + ch1);
                ldsm4(al[1], uAl + rA1 * 256 + ch1);
            }
            uint32_t bh[8][2], bl[8][2];
            #pragma unroll
            for (int p = 0; p < 4; p++) {
                uint32_t ch = (uint32_t)((kk * 2 + cB) ^ (rB[p] & 7)) << 4;
                uint32_t r[4];
                ldsm4(r, uBh + rB[p] * 256 + ch);
                bh[2*p][0] = r[0]; bh[2*p][1] = r[1];
                bh[2*p+1][0] = r[2]; bh[2*p+1][1] = r[3];
                ldsm4(r, uBl + rB[p] * 256 + ch);
                bl[2*p][0] = r[0]; bl[2*p][1] = r[1];
                bl[2*p+1][0] = r[2]; bl[2*p+1][1] = r[3];
            }
            #pragma unroll
            for (int ss = 0; ss < 2; ss++)
                #pragma unroll
                for (int j = 0; j < 8; j++)
                    mma_bf16(acc[ss][j], ah[ss], bh[j]);
            #pragma unroll
            for (int ss = 0; ss < 2; ss++)
                #pragma unroll
                for (int j = 0; j < 8; j++)
                    mma_bf16(acc[ss][j], ah[ss], bl[j]);
            #pragma unroll
            for (int ss = 0; ss < 2; ss++)
                #pragma unroll
                for (int j = 0; j < 8; j++)
                    mma_bf16(acc[ss][j], al[ss], bh[j]);
        }
        __syncthreads();   // all warps done reading A before D overlays it

        // ---- store D fragments to SMEM (f32, swizzled) ---------------------
        #pragma unroll
        for (int ss = 0; ss < 2; ss++) {
            int r0 = warpM * 32 + ss * 16 + (lane >> 2);
            #pragma unroll
            for (int j = 0; j < 8; j++) {
                int c0 = warpN * 64 + j * 8 + (lane & 3) * 2;
                *(float2*)(sD + sw_f32(r0, c0)) =
                    make_float2(acc[ss][j][0], acc[ss][j][1]);
                *(float2*)(sD + sw_f32(r0 + 8, c0)) =
                    make_float2(acc[ss][j][2], acc[ss][j][3]);
            }
        }
        __syncthreads();

        // ---- epilogue: silu+gate+gamma+scatter (warp w: rows w*16..+15) ----
        for (int g = 0; g < 16; g++) {
            int row = wid * 16 + g;
            int ddv = sdd[row];
            int okv = shv[row];
            float sgv = ssg[row];
            float4 d = *(const float4*)(sD + (uint32_t)(row * 512 +
                                        ((lane ^ (row & 7)) << 4)));
            float4 m;
            m.x = silu_f(d.x + b2v.x) * sgv;
            m.y = silu_f(d.y + b2v.y) * sgv;
            m.z = silu_f(d.z + b2v.z) * sgv;
            m.w = silu_f(d.w + b2v.w) * sgv;

            float p = m.x * wcv.x + m.y * wcv.y + m.z * wcv.z + m.w * wcv.w;
            #pragma unroll
            for (int o = 16; o; o >>= 1)
                p += __shfl_xor_sync(0xffffffffu, p, o);

            if (okv) {
                red_add_v4(g_msum + (size_t)ddv * 128 + lane * 4, m);
                if (lane == 0) {
                    float gamma = p + bcv;
                    atomicAdd(g_coord + ddv * 3 + 0, gamma * sdx[row]);
                    atomicAdd(g_coord + ddv * 3 + 1, gamma * sdy[row]);
                    atomicAdd(g_coord + ddv * 3 + 2, gamma * sdz[row]);
                    atomicAdd(g_deg + ddv, 1.0f);
                }
            }
        }
        __syncthreads();   // meta/A reused next tile
    }
}

// ------------------------------- node ---------------------------------------
__global__ __launch_bounds__(TPB_N, 1)
void node_kernel(const float* __restrict__ x, const float* __restrict__ pos,
                 const float* __restrict__ Wn1, const float* __restrict__ bn1,
                 const float* __restrict__ Wn2, const float* __restrict__ bn2,
                 float* __restrict__ xout, float* __restrict__ posout,
                 int N)
{
    extern __shared__ float sm[];
    float* sW1 = sm;
    float* sW2 = sW1 + 128 * 256;
    float* sb1 = sW2 + 64 * 256;
    float* sb2 = sb1 + 128;
    float* sE  = sb2 + 128;

    const int tid = threadIdx.x;
    for (int idx = tid; idx < 256 * 128; idx += TPB_N) {
        int k = idx >> 7, j = idx & 127;
        sW1[wswz(k, j)] = Wn1[idx];
    }
    for (int idx = tid; idx < 128 * 128; idx += TPB_N) {
        int k = idx >> 7, j = idx & 127;
        sW2[wswz(k, j)] = Wn2[idx];
    }
    for (int i = tid; i < 128; i += TPB_N) { sb1[i] = bn1[i]; sb2[i] = bn2[i]; }
    __syncthreads();

    const int lane = tid & 31;
    const int w    = tid >> 5;
    float* eb = sE + w * (ND * 128);

    const int wofs = lane * 8;
    const int s4   = ((lane >> 2) & 1) * 4;
    const float4 sb1v = *(const float4*)(sb1 + lane * 4);
    const float4 sb2v = *(const float4*)(sb2 + lane * 4);

    const int bstride = gridDim.x * NW_N * ND;
    for (int b0 = (blockIdx.x * NW_N + w) * ND; b0 < N; b0 += bstride) {

        int nm = b0 + lane;
        float inv = 1.0f;
        if (lane < ND && nm < N) inv = 1.0f / fmaxf(g_deg[nm], 1.0f);

        unsigned long long acc[ND][4];
        #pragma unroll
        for (int g = 0; g < ND; g++)
            acc[g][0] = acc[g][1] = acc[g][2] = acc[g][3] = 0ull;

        __syncwarp();
        #pragma unroll
        for (int g = 0; g < ND; g++) {
            int ng = b0 + g; if (ng >= N) ng = N - 1;
            *(float4*)(eb + g * 128 + lane * 4) =
                *(const float4*)(x + (size_t)ng * 128 + lane * 4);
        }
        __syncwarp();
        #pragma unroll 4
        for (int k4 = 0; k4 < 32; k4++)
            gemv_step<ND>(sW1 + (k4 * 2) * 256 + wofs, s4, eb, 128, k4 * 4, acc);

        __syncwarp();
        #pragma unroll
        for (int g = 0; g < ND; g++) {
            int ng = b0 + g; if (ng >= N) ng = N - 1;
            float ig = __shfl_sync(0xffffffffu, inv, g);
            float4 ms = *(const float4*)(g_msum + (size_t)ng * 128 + lane * 4);
            ms.x *= ig; ms.y *= ig; ms.z *= ig; ms.w *= ig;
            *(float4*)(eb + g * 128 + lane * 4) = ms;
        }
        __syncwarp();
        #pragma unroll 4
        for (int k4 = 0; k4 < 32; k4++)
            gemv_step<ND>(sW1 + ((k4 + 32) * 2) * 256 + wofs, s4, eb, 128, k4 * 4, acc);

        __syncwarp();
        #pragma unroll
        for (int g = 0; g < ND; g++) {
            float4 h;
            h.x = silu_f(lohi_sum(acc[g][0]) + sb1v.x);
            h.y = silu_f(lohi_sum(acc[g][1]) + sb1v.y);
            h.z = silu_f(lohi_sum(acc[g][2]) + sb1v.z);
            h.w = silu_f(lohi_sum(acc[g][3]) + sb1v.w);
            *(float4*)(eb + g * 128 + lane * 4) = h;
            acc[g][0] = acc[g][1] = acc[g][2] = acc[g][3] = 0ull;
        }
        __syncwarp();

        #pragma unroll 4
        for (int k4 = 0; k4 < 32; k4++)
            gemv_step<ND>(sW2 + (k4 * 2) * 256 + wofs, s4, eb, 128, k4 * 4, acc);

        #pragma unroll
        for (int g = 0; g < ND; g++) {
            int ng = b0 + g;
            if (ng < N) {
                float4 o;
                o.x = lohi_sum(acc[g][0]) + sb2v.x;
                o.y = lohi_sum(acc[g][1]) + sb2v.y;
                o.z = lohi_sum(acc[g][2]) + sb2v.z;
                o.w = lohi_sum(acc[g][3]) + sb2v.w;
                *(float4*)(xout + (size_t)ng * 128 + lane * 4) = o;
                float ig = __shfl_sync(0xffffffffu, inv, g);
                if (lane < 3)
                    posout[ng * 3 + lane] =
                        pos[ng * 3 + lane] + g_coord[ng * 3 + lane] * ig;
            }
        }
    }
}

// ------------------------------- launch --------------------------------------
extern "C" void kernel_launch(void* const* d_in, const int* in_sizes, int n_in,
                              void* d_out, int out_size) {
    const float* x     = (const float*)d_in[0];
    const float* pos   = (const float*)d_in[1];
    const void*  ei    = d_in[2];
    const float* eattr = (const float*)d_in[3];
    const float* s     = (const float*)d_in[4];
    const float* We1   = (const float*)d_in[5];
    const float* be1   = (const float*)d_in[6];
    const float* We2   = (const float*)d_in[7];
    const float* be2   = (const float*)d_in[8];
    const float* Wn1   = (const float*)d_in[9];
    const float* bn1   = (const float*)d_in[10];
    const float* Wn2   = (const float*)d_in[11];
    const float* bn2   = (const float*)d_in[12];
    const float* Wc    = (const float*)d_in[13];
    const float* bc    = (const float*)d_in[14];

    const int N = in_sizes[0] / 128;
    const int E = in_sizes[2] / 2;

    float* xout   = (float*)d_out;
    float* posout = (float*)d_out + (size_t)N * 128;

    int dev = 0, nsm = 148;
    cudaGetDevice(&dev);
    cudaDeviceGetAttribute(&nsm, cudaDevAttrMultiProcessorCount, dev);

    const size_t smem_pre  = (size_t)(64 * 256 + 64 * 256 +
                                      NW_P * ND_P * 128) * sizeof(float);  // 163,840
    const size_t smem_edge = 131072 + 11 * 128 * 4 + 3 * 128 * 4;          // 138,240
    const size_t smem_node = (size_t)(128 * 256 + 64 * 256 + 2 * 128 +
                                      NW_N * ND * 128) * sizeof(float);    // 230,400

    cudaFuncSetAttribute(pre_kernel,  cudaFuncAttributeMaxDynamicSharedMemorySize,
                         (int)smem_pre);
    cudaFuncSetAttribute(edge_kernel, cudaFuncAttributeMaxDynamicSharedMemorySize,
                         (int)smem_edge);
    cudaFuncSetAttribute(node_kernel, cudaFuncAttributeMaxDynamicSharedMemorySize,
                         (int)smem_node);

    zero_kernel<<<512, 256>>>(N);
    detect_kernel<<<16, 256>>>((const unsigned int*)ei, E);
    pre_kernel<<<nsm, TPB_P, smem_pre>>>(x, We1, N);
    edge_kernel<<<nsm, TPB_E, smem_edge>>>(pos,
                                           (const int*)ei, (const long long*)ei,
                                           eattr, s,
                                           We1, be1, We2, be2, Wc, bc, E, N);
    node_kernel<<<nsm, TPB_N, smem_node>>>(x, pos, Wn1, bn1, Wn2, bn2,
                                           xout, posout, N);
}